// round 10
// baseline (speedup 1.0000x reference)
#include <cuda_runtime.h>
#include <math.h>

// Problem constants (fixed shapes from reference setup_inputs)
#define BB   64      // batch
#define TTT  256     // target timesteps
#define SST  1024    // source timesteps
#define HHH  512     // hidden
#define EEE  512     // embed dim
#define VVV  32      // vocab  (KEY: tiny -> gi becomes a 32-row table)
#define G3   1536    // 3*H
#define OOO  31      // fc outputs
#define NCH  8       // attention s-chunks per batch
#define CHS  128     // SST / NCH

// ---------------- scratch (static device globals; no allocation) ----------
__device__ float g_GiT [VVV * G3];        // gi table: embed@W_ih^T + b_ih  (192KB)
__device__ float g_h   [2][BB * HHH];     // ping-pong hidden state
__device__ float g_gh  [BB * G3];         // h @ W_hh^T (pre-bias)
__device__ float g_pm  [BB * NCH];        // per-chunk softmax max
__device__ float g_pl  [BB * NCH];        // per-chunk softmax denom (rel. to pm)
__device__ float g_pctx[BB * NCH * HHH];  // per-chunk unnormalized ctx

// ---------------- helpers -------------------------------------------------
__device__ __forceinline__ float dot4(float4 a, float4 b) {
    return a.x*b.x + a.y*b.y + a.z*b.z + a.w*b.w;
}
__device__ __forceinline__ float wsum(float v) {
    #pragma unroll
    for (int o = 16; o; o >>= 1) v += __shfl_xor_sync(0xffffffffu, v, o);
    return v;
}

// ---------------- A1: GiTable[v][j] = dot(embed[v], W_ih[j]) + b_ih[j] ----
// 1536 warp-tasks (one per j row); each warp keeps its W_ih row in registers
// and loops over the 32 vocab entries (embed rows are 64KB total -> L1-hot).
__global__ void k_gitable(const float* __restrict__ embed,
                          const float* __restrict__ Wih,
                          const float* __restrict__ bih) {
    int gw   = (blockIdx.x * blockDim.x + threadIdx.x) >> 5;
    int lane = threadIdx.x & 31;
    if (gw >= G3) return;
    const float4* wr = (const float4*)(Wih + (size_t)gw * EEE);
    float4 w0 = wr[lane], w1 = wr[lane+32], w2 = wr[lane+64], w3 = wr[lane+96];
    float bj = bih[gw];
    for (int v = 0; v < VVV; v++) {
        const float4* er = (const float4*)(embed + (size_t)v * EEE);
        float4 e0 = er[lane], e1 = er[lane+32], e2 = er[lane+64], e3 = er[lane+96];
        float acc = dot4(w0,e0) + dot4(w1,e1) + dot4(w2,e2) + dot4(w3,e3);
        acc = wsum(acc);
        if (lane == 0) g_GiT[v * G3 + gw] = acc + bj;
    }
}

// ---------------- K1 body: gh = h @ W_hh^T  (no bias) ---------------------
// 96 blocks = 8 b-tiles x 12 j-tiles. Block stages 8 hidden rows (16KB smem).
// Warp computes 16 W_hh rows: row held in registers (4x LDG.128, coalesced),
// dotted against 8 batches via float4 LDS + warp reduction.
// W_hh L2 traffic = 3MB * 8 = 24MB per step (sub-microsecond on L2).
__device__ __forceinline__ void k1_body(int bid, const float* __restrict__ hprev,
                                        const float* __restrict__ Whh, float* sh) {
    int tid  = threadIdx.x;
    int jblk = bid % 12;
    int b0   = (bid / 12) * 8;
    const float4* src = (const float4*)(hprev + (size_t)b0 * HHH);
    for (int i = tid; i < 8 * HHH / 4; i += 256) ((float4*)sh)[i] = src[i];
    __syncthreads();
    int w = tid >> 5, lane = tid & 31;
    for (int r = 0; r < 16; r++) {
        int j = jblk * 128 + w * 16 + r;
        const float4* wr = (const float4*)(Whh + (size_t)j * HHH);
        float4 w0 = wr[lane], w1 = wr[lane+32], w2 = wr[lane+64], w3 = wr[lane+96];
        #pragma unroll
        for (int b = 0; b < 8; b++) {
            const float4* hr = (const float4*)(sh + b * HHH);
            float acc = dot4(w0, hr[lane])    + dot4(w1, hr[lane+32])
                      + dot4(w2, hr[lane+64]) + dot4(w3, hr[lane+96]);
            acc = wsum(acc);
            if (lane == 0) g_gh[(size_t)(b0 + b) * G3 + j] = acc;
        }
    }
}

__global__ void k1_pro(const float* __restrict__ hlast, const float* __restrict__ Whh) {
    __shared__ float sh[8 * HHH];
    k1_body(blockIdx.x, hlast, Whh, sh);
}

// ---------------- K2: gates + h_new + online-softmax attention ------------
// grid = 64 b x 8 chunks. Each block first (redundantly, deterministically)
// computes h_new[b] into smem from g_gh + GiTable, then does a single pass
// over its 128 encoder rows: each row is loaded ONCE into registers and used
// for both the score dot and the weighted ctx accumulate (flash-style).
__global__ void k2_attn(const float* __restrict__ enc,
                        const float* __restrict__ hlast,
                        const float* __restrict__ bhh,
                        const int*   __restrict__ trg,
                        const int*   __restrict__ slen,
                        int t) {
    __shared__ float sh_h[HHH];            // h_new for this batch
    __shared__ float sm_ctx[NCH][HHH];     // per-warp scaled ctx (16KB)
    __shared__ float sm_m[8], sm_l[8];
    int b = blockIdx.x >> 3;
    int c = blockIdx.x & 7;
    int tid = threadIdx.x;

    // ---- GRU gates -> h_new ----
    const float* hprev = (t == 0) ? (hlast + (size_t)b * HHH) : (&g_h[t & 1][(size_t)b * HHH]);
    int tok = trg[b * TTT + t];
    const float* gi = g_GiT + (size_t)tok * G3;
    const float* gh = g_gh + (size_t)b * G3;
    for (int j = tid; j < HHH; j += 256) {
        float r = 1.f / (1.f + expf(-(gi[j]       + gh[j]       + bhh[j])));
        float z = 1.f / (1.f + expf(-(gi[j+HHH]   + gh[j+HHH]   + bhh[j+HHH])));
        float n = tanhf(gi[j+2*HHH] + r * (gh[j+2*HHH] + bhh[j+2*HHH]));
        float hn = (1.f - z) * n + z * hprev[j];
        sh_h[j] = hn;
        if (c == 0) g_h[(t + 1) & 1][(size_t)b * HHH + j] = hn;  // persist for K3/K1
    }
    __syncthreads();

    // ---- online softmax attention over s-chunk ----
    int w = tid >> 5, lane = tid & 31;
    int sl = slen[b];
    const float4* hv = (const float4*)sh_h;
    float4 h0 = hv[lane], h1 = hv[lane+32], h2 = hv[lane+64], h3 = hv[lane+96];
    float m = -1e30f, l = 0.f;
    float4 c0 = {0,0,0,0}, c1 = {0,0,0,0}, c2 = {0,0,0,0}, c3 = {0,0,0,0};
    int s0 = c * CHS + w * 16;
    #pragma unroll 1
    for (int i = 0; i < 16; i++) {
        int s = s0 + i;
        if (s >= sl) break;                                  // warp-uniform
        const float4* er = (const float4*)(enc + ((size_t)b * SST + s) * HHH);
        float4 e0 = er[lane], e1 = er[lane+32], e2 = er[lane+64], e3 = er[lane+96];
        float d = dot4(e0,h0) + dot4(e1,h1) + dot4(e2,h2) + dot4(e3,h3);
        d = wsum(d);                                         // uniform score
        float mn   = fmaxf(m, d);
        float corr = expf(m - mn);
        float p    = expf(d - mn);
        l = l * corr + p;
        c0.x = c0.x*corr + p*e0.x; c0.y = c0.y*corr + p*e0.y;
        c0.z = c0.z*corr + p*e0.z; c0.w = c0.w*corr + p*e0.w;
        c1.x = c1.x*corr + p*e1.x; c1.y = c1.y*corr + p*e1.y;
        c1.z = c1.z*corr + p*e1.z; c1.w = c1.w*corr + p*e1.w;
        c2.x = c2.x*corr + p*e2.x; c2.y = c2.y*corr + p*e2.y;
        c2.z = c2.z*corr + p*e2.z; c2.w = c2.w*corr + p*e2.w;
        c3.x = c3.x*corr + p*e3.x; c3.y = c3.y*corr + p*e3.y;
        c3.z = c3.z*corr + p*e3.z; c3.w = c3.w*corr + p*e3.w;
        m = mn;
    }
    if (lane == 0) { sm_m[w] = m; sm_l[w] = l; }
    __syncthreads();
    float M = sm_m[0];
    #pragma unroll
    for (int k = 1; k < 8; k++) M = fmaxf(M, sm_m[k]);
    float L = 0.f;
    #pragma unroll
    for (int k = 0; k < 8; k++) L += sm_l[k] * expf(sm_m[k] - M);
    float f = expf(m - M);   // per-warp rescale (exp(-1e30 - M) == 0, no NaN)
    c0.x*=f; c0.y*=f; c0.z*=f; c0.w*=f;  c1.x*=f; c1.y*=f; c1.z*=f; c1.w*=f;
    c2.x*=f; c2.y*=f; c2.z*=f; c2.w*=f;  c3.x*=f; c3.y*=f; c3.z*=f; c3.w*=f;
    float4* cw = (float4*)(sm_ctx[w]);
    cw[lane] = c0; cw[lane+32] = c1; cw[lane+64] = c2; cw[lane+96] = c3;
    __syncthreads();
    for (int d = tid; d < HHH; d += 256) {
        float s = 0.f;
        #pragma unroll
        for (int k = 0; k < 8; k++) s += sm_ctx[k][d];
        g_pctx[((size_t)b * NCH + c) * HHH + d] = s;
    }
    if (tid == 0) { g_pm[b * NCH + c] = M; g_pl[b * NCH + c] = L; }
}

// ---------------- K3 (blocks 0..63) fused with next-step K1 (64..159) -----
// K3: combine 8 chunk-partials -> ctx, then out = fc([h_new; ctx]) with the
// trg_len mask (pad timesteps written as exact 0.0).
__global__ void k31(const float* __restrict__ Whh,
                    const float* __restrict__ fcW,
                    const float* __restrict__ fcb,
                    const int*   __restrict__ tlen,
                    float*       __restrict__ out,
                    int t) {
    __shared__ float sh[8 * HHH];  // K1 uses all 16KB; K3 uses first 4KB as [h;ctx]
    int tid = threadIdx.x;
    if (blockIdx.x >= 64) {        // gh for step t+1 (depends only on h(t))
        k1_body(blockIdx.x - 64, &g_h[(t + 1) & 1][0], Whh, sh);
        return;
    }
    int b = blockIdx.x;
    float pm[8], pl[8];
    #pragma unroll
    for (int k = 0; k < 8; k++) { pm[k] = g_pm[b*NCH + k]; pl[k] = g_pl[b*NCH + k]; }
    float M = pm[0];
    #pragma unroll
    for (int k = 1; k < 8; k++) M = fmaxf(M, pm[k]);
    float L = 0.f;
    #pragma unroll
    for (int k = 0; k < 8; k++) L += pl[k] * expf(pm[k] - M);
    float invL = 1.f / L;          // source_len >= 1 -> L > 0
    float* cat = sh;               // [0..511] = h_new, [512..1023] = ctx
    const float* hn = &g_h[(t + 1) & 1][(size_t)b * HHH];
    for (int d = tid; d < HHH; d += 256) {
        cat[d] = hn[d];
        float s = 0.f;
        #pragma unroll
        for (int k = 0; k < 8; k++)
            s += expf(pm[k] - M) * g_pctx[((size_t)b * NCH + k) * HHH + d];
        cat[HHH + d] = s * invL;
    }
    __syncthreads();
    int w = tid >> 5, lane = tid & 31;
    int valid = (t < tlen[b]);
    for (int oo = 0; oo < 4; oo++) {
        int oi = w * 4 + oo;
        if (oi >= OOO) break;
        const float4* fr = (const float4*)(fcW + (size_t)oi * 2 * HHH);
        const float4* cv = (const float4*)cat;
        float acc = 0.f;
        #pragma unroll
        for (int seg = 0; seg < 8; seg++) acc += dot4(fr[seg*32 + lane], cv[seg*32 + lane]);
        acc = wsum(acc);
        if (lane == 0)
            out[((size_t)b * TTT + t) * OOO + oi] = valid ? (acc + fcb[oi]) : 0.0f;
    }
}

// ---------------- launch ---------------------------------------------------
extern "C" void kernel_launch(void* const* d_in, const int* in_sizes, int n_in,
                              void* d_out, int out_size) {
    const int*   trg   = (const int*)  d_in[0];
    const int*   tlen  = (const int*)  d_in[1];
    const int*   slen  = (const int*)  d_in[2];
    const float* enc   = (const float*)d_in[3];
    const float* hlast = (const float*)d_in[4];   // (1,B,H) == (B,H)
    const float* embed = (const float*)d_in[5];
    const float* Wih   = (const float*)d_in[6];
    const float* Whh   = (const float*)d_in[7];
    const float* bih   = (const float*)d_in[8];
    const float* bhh   = (const float*)d_in[9];
    const float* fcW   = (const float*)d_in[10];
    const float* fcb   = (const float*)d_in[11];
    float*       out   = (float*)d_out;

    k_gitable<<<192, 256>>>(embed, Wih, bih);   // 1536 j-rows x 32 vocab
    k1_pro   <<<96, 256>>>(hlast, Whh);         // gh for t=0
    for (int t = 0; t < TTT; t++) {
        k2_attn<<<512, 256>>>(enc, hlast, bhh, trg, slen, t);
        k31    <<<160, 256>>>(Whh, fcW, fcb, tlen, out, t);
    }
}